// round 1
// baseline (speedup 1.0000x reference)
#include <cuda_runtime.h>

#define N_NODES 50000
#define D 128
#define NE 800000
#define BM 128
#define LDA 132                       // padded smem stride (floats), 16B aligned
#define GEMM_SMEM ((BM + D) * LDA * 4)

// -------- device scratch (static allocation is allowed) --------
__device__ float g_h[(size_t)N_NODES * D];    // h = x @ W
__device__ float g_agg[(size_t)N_NODES * D];  // aggregation accumulator
__device__ float g_buf[(size_t)N_NODES * D];  // layer output / next input
__device__ float g_dis[N_NODES];              // deg -> rsqrt(deg+1)

// -------- degree / normalization --------
__global__ void zero_dis_kernel() {
    int i = blockIdx.x * blockDim.x + threadIdx.x;
    if (i < N_NODES) g_dis[i] = 0.0f;
}

__global__ void deg_kernel(const int* __restrict__ dst) {
    int e = blockIdx.x * blockDim.x + threadIdx.x;
    if (e < NE) atomicAdd(&g_dis[dst[e]], 1.0f);
}

__global__ void rsqrt_kernel() {
    int i = blockIdx.x * blockDim.x + threadIdx.x;
    if (i < N_NODES) g_dis[i] = rsqrtf(g_dis[i] + 1.0f);
}

// -------- GEMM: C[M,128] = A[M,128] @ W[128,128] (+ epilogue) --------
// mode 0: C = h, C2 = h * dis[m]^2        (GCN pre-aggregation)
// mode 1: C = relu(h + bias)
// mode 2: C = h + bias
__global__ __launch_bounds__(256, 1)
void gemm_kernel(const float* __restrict__ A, const float* __restrict__ W,
                 const float* __restrict__ bias,
                 float* __restrict__ C, float* __restrict__ C2,
                 int M, int mode)
{
    extern __shared__ float smem[];
    float* As = smem;            // BM x LDA
    float* Ws = smem + BM * LDA; // D  x LDA

    const int tid = threadIdx.x;
    const int m0  = blockIdx.x * BM;

    // load A tile (BM x 128), zero-fill out-of-range rows
    const float4 z4 = make_float4(0.f, 0.f, 0.f, 0.f);
#pragma unroll
    for (int i = 0; i < 16; i++) {
        int f = i * 256 + tid;            // float4 index into tile
        int m  = f >> 5;                  // 32 float4 per row
        int k4 = f & 31;
        float4 v = (m0 + m < M)
            ? __ldg((const float4*)(A + (size_t)(m0 + m) * D) + k4) : z4;
        *(float4*)(As + m * LDA + k4 * 4) = v;
    }
    // load W (128 x 128)
#pragma unroll
    for (int i = 0; i < 16; i++) {
        int f = i * 256 + tid;
        int k  = f >> 5;
        int n4 = f & 31;
        float4 v = __ldg((const float4*)(W + (size_t)k * D) + n4);
        *(float4*)(Ws + k * LDA + n4 * 4) = v;
    }
    __syncthreads();

    const int ty  = tid >> 4;
    const int tx  = tid & 15;
    const int row = ty * 8;
    const int col = tx * 8;

    float acc[8][8];
#pragma unroll
    for (int i = 0; i < 8; i++)
#pragma unroll
        for (int j = 0; j < 8; j++) acc[i][j] = 0.0f;

#pragma unroll 4
    for (int k = 0; k < D; k++) {
        float b[8];
        float4 t0 = *(const float4*)(Ws + k * LDA + col);
        float4 t1 = *(const float4*)(Ws + k * LDA + col + 4);
        b[0] = t0.x; b[1] = t0.y; b[2] = t0.z; b[3] = t0.w;
        b[4] = t1.x; b[5] = t1.y; b[6] = t1.z; b[7] = t1.w;
        float a[8];
#pragma unroll
        for (int i = 0; i < 8; i++) a[i] = As[(row + i) * LDA + k];
#pragma unroll
        for (int i = 0; i < 8; i++)
#pragma unroll
            for (int j = 0; j < 8; j++) acc[i][j] += a[i] * b[j];
    }

    // epilogue
    if (mode == 0) {
#pragma unroll
        for (int i = 0; i < 8; i++) {
            int m = m0 + row + i;
            if (m >= M) break;
            float d = g_dis[m];
            float d2 = d * d;
            float* cp  = C  + (size_t)m * D + col;
            float* cp2 = C2 + (size_t)m * D + col;
            float4 v0 = make_float4(acc[i][0], acc[i][1], acc[i][2], acc[i][3]);
            float4 v1 = make_float4(acc[i][4], acc[i][5], acc[i][6], acc[i][7]);
            *(float4*)cp       = v0;
            *(float4*)(cp + 4) = v1;
            float4 w0 = make_float4(v0.x * d2, v0.y * d2, v0.z * d2, v0.w * d2);
            float4 w1 = make_float4(v1.x * d2, v1.y * d2, v1.z * d2, v1.w * d2);
            *(float4*)cp2       = w0;
            *(float4*)(cp2 + 4) = w1;
        }
    } else {
        float bb[8];
        float4 t0 = __ldg((const float4*)(bias + col));
        float4 t1 = __ldg((const float4*)(bias + col + 4));
        bb[0]=t0.x; bb[1]=t0.y; bb[2]=t0.z; bb[3]=t0.w;
        bb[4]=t1.x; bb[5]=t1.y; bb[6]=t1.z; bb[7]=t1.w;
#pragma unroll
        for (int i = 0; i < 8; i++) {
            int m = m0 + row + i;
            if (m >= M) break;
            float out[8];
#pragma unroll
            for (int j = 0; j < 8; j++) {
                float v = acc[i][j] + bb[j];
                out[j] = (mode == 1) ? fmaxf(v, 0.0f) : v;
            }
            float* cp = C + (size_t)m * D + col;
            *(float4*)cp       = make_float4(out[0], out[1], out[2], out[3]);
            *(float4*)(cp + 4) = make_float4(out[4], out[5], out[6], out[7]);
        }
    }
}

// -------- edge scatter: agg[dst] += h[src] * dis[src]*dis[dst] --------
// one warp per edge; lane handles 4 floats -> one float4 vector atomic (RED.128)
__global__ void scatter_kernel(const int* __restrict__ src, const int* __restrict__ dst) {
    long long idx = (long long)blockIdx.x * blockDim.x + threadIdx.x;
    int e    = (int)(idx >> 5);
    int lane = (int)(idx & 31);
    if (e >= NE) return;
    int s = __ldg(src + e);
    int d = __ldg(dst + e);
    float norm = __ldg(&g_dis[s]) * __ldg(&g_dis[d]);
    float4 v = __ldg((const float4*)(g_h + (size_t)s * D) + lane);
    v.x *= norm; v.y *= norm; v.z *= norm; v.w *= norm;
    atomicAdd(((float4*)(g_agg + (size_t)d * D)) + lane, v);
}

// -------- finalize: buf = relu(agg + bias) --------
__global__ void finalize_kernel(const float* __restrict__ bias, float* __restrict__ out) {
    int i = blockIdx.x * blockDim.x + threadIdx.x;
    if (i < N_NODES * D) {
        float v = g_agg[i] + __ldg(&bias[i & (D - 1)]);
        out[i] = fmaxf(v, 0.0f);
    }
}

extern "C" void kernel_launch(void* const* d_in, const int* in_sizes, int n_in,
                              void* d_out, int out_size)
{
    const float* x    = (const float*)d_in[0];
    const int*   ei   = (const int*)  d_in[1];
    const float* xa   = (const float*)d_in[2];
    const int*   eia  = (const int*)  d_in[3];
    const float* W_in = (const float*)d_in[4];
    const float* b_in = (const float*)d_in[5];
    const float* W_h  = (const float*)d_in[6];
    const float* b_h  = (const float*)d_in[7];
    const float* W_out= (const float*)d_in[8];
    const float* b_out= (const float*)d_in[9];
    const float* Wf1  = (const float*)d_in[10];
    const float* bf1  = (const float*)d_in[11];
    const float* Wf2  = (const float*)d_in[12];
    const float* bf2  = (const float*)d_in[13];
    float* out = (float*)d_out;

    cudaFuncSetAttribute(gemm_kernel,
        cudaFuncAttributeMaxDynamicSharedMemorySize, GEMM_SMEM);

    float *hp, *aggp, *bufp;
    cudaGetSymbolAddress((void**)&hp,   g_h);
    cudaGetSymbolAddress((void**)&aggp, g_agg);
    cudaGetSymbolAddress((void**)&bufp, g_buf);

    const int gemm_blocks = (N_NODES + BM - 1) / BM;          // 391
    const int node_blocks = (N_NODES + 255) / 256;            // 196
    const int edge_blocks = (NE + 255) / 256;                 // 3125
    const int scat_blocks = (int)(((long long)NE * 32 + 255) / 256); // 100000
    const int elem_blocks = (N_NODES * D + 255) / 256;        // 25000

    const float* Wl[3] = {W_in, W_h, W_out};
    const float* bl[3] = {b_in, b_h, b_out};

    for (int g = 0; g < 2; g++) {
        const float* X   = g ? xa : x;
        const int*   src = (g ? eia : ei);
        const int*   dst = src + NE;
        float* OUT = out + (size_t)g * N_NODES * D;

        // normalization coefficients
        zero_dis_kernel<<<node_blocks, 256>>>();
        deg_kernel<<<edge_blocks, 256>>>(dst);
        rsqrt_kernel<<<node_blocks, 256>>>();

        // 3 GCN layers
        const float* in = X;
        for (int l = 0; l < 3; l++) {
            gemm_kernel<<<gemm_blocks, 256, GEMM_SMEM>>>(
                in, Wl[l], nullptr, hp, aggp, N_NODES, 0);
            scatter_kernel<<<scat_blocks, 256>>>(src, dst);
            finalize_kernel<<<elem_blocks, 256>>>(bl[l], bufp);
            in = bufp;
        }

        // MLP head
        gemm_kernel<<<gemm_blocks, 256, GEMM_SMEM>>>(
            bufp, Wf1, bf1, hp, nullptr, N_NODES, 1);
        gemm_kernel<<<gemm_blocks, 256, GEMM_SMEM>>>(
            hp, Wf2, bf2, OUT, nullptr, N_NODES, 2);
    }
}

// round 2
// speedup vs baseline: 1.2100x; 1.2100x over previous
#include <cuda_runtime.h>

#define N_NODES 50000
#define D 128
#define NE 800000
#define BM 128
#define LDA 132
#define GEMM_SMEM ((BM + D) * LDA * 4)
#define NTHREADS 512
#define SCAN_NBLK ((N_NODES + 1023) / 1024)   // 49

// -------- device scratch --------
__device__ float g_h[(size_t)N_NODES * D];
__device__ float g_agg[(size_t)N_NODES * D];   // init (self-loop + bias), then gather target
__device__ float g_buf[(size_t)N_NODES * D];
__device__ float g_dis[N_NODES];
__device__ int   g_cnt[N_NODES];
__device__ int   g_off[N_NODES];
__device__ int   g_cur[N_NODES];
__device__ int   g_csrc[NE];
__device__ float g_cw[NE];
__device__ int   g_bsum[64];

// -------- CSR build --------
__global__ void zero_kernel() {
    int i = blockIdx.x * blockDim.x + threadIdx.x;
    if (i < N_NODES) { g_cnt[i] = 0; g_cur[i] = 0; }
}

__global__ void count_kernel(const int* __restrict__ dst) {
    int e = blockIdx.x * blockDim.x + threadIdx.x;
    if (e < NE) atomicAdd(&g_cnt[dst[e]], 1);
}

__global__ void dis_kernel() {
    int i = blockIdx.x * blockDim.x + threadIdx.x;
    if (i < N_NODES) g_dis[i] = rsqrtf((float)g_cnt[i] + 1.0f);
}

__global__ void scan1_kernel() {
    __shared__ int sh[1024];
    int i = blockIdx.x * 1024 + threadIdx.x;
    int v = (i < N_NODES) ? g_cnt[i] : 0;
    sh[threadIdx.x] = v;
    __syncthreads();
#pragma unroll
    for (int ofs = 1; ofs < 1024; ofs <<= 1) {
        int t = (threadIdx.x >= ofs) ? sh[threadIdx.x - ofs] : 0;
        __syncthreads();
        sh[threadIdx.x] += t;
        __syncthreads();
    }
    if (i < N_NODES) g_off[i] = sh[threadIdx.x] - v;   // exclusive
    if (threadIdx.x == 1023) g_bsum[blockIdx.x] = sh[1023];
}

__global__ void scan2_kernel() {
    __shared__ int sh[64];
    int v = (threadIdx.x < SCAN_NBLK) ? g_bsum[threadIdx.x] : 0;
    sh[threadIdx.x] = v;
    __syncthreads();
#pragma unroll
    for (int ofs = 1; ofs < 64; ofs <<= 1) {
        int t = (threadIdx.x >= ofs) ? sh[threadIdx.x - ofs] : 0;
        __syncthreads();
        sh[threadIdx.x] += t;
        __syncthreads();
    }
    if (threadIdx.x < SCAN_NBLK) g_bsum[threadIdx.x] = sh[threadIdx.x] - v;  // exclusive
}

__global__ void scan3_kernel() {
    int i = blockIdx.x * blockDim.x + threadIdx.x;
    if (i < N_NODES) g_off[i] += g_bsum[i >> 10];
}

__global__ void fill_kernel(const int* __restrict__ src, const int* __restrict__ dst) {
    int e = blockIdx.x * blockDim.x + threadIdx.x;
    if (e >= NE) return;
    int s = src[e], d = dst[e];
    int p = g_off[d] + atomicAdd(&g_cur[d], 1);
    g_csrc[p] = s;
    g_cw[p]   = g_dis[s] * g_dis[d];
}

// -------- GEMM: C[M,128] = A[M,128] @ W[128,128] (+ epilogue) --------
// mode 0: C = h, C2 = h*dis[m]^2 + bias   (GCN: self-loop + bias pre-init)
// mode 1: C = relu(h + bias)
// mode 2: C = h + bias
__global__ __launch_bounds__(NTHREADS, 1)
void gemm_kernel(const float* __restrict__ A, const float* __restrict__ W,
                 const float* __restrict__ bias,
                 float* __restrict__ C, float* __restrict__ C2,
                 int M, int mode)
{
    extern __shared__ float smem[];
    float* As = smem;            // BM x LDA
    float* Ws = smem + BM * LDA; // D  x LDA

    const int tid = threadIdx.x;
    const int m0  = blockIdx.x * BM;

    const float4 z4 = make_float4(0.f, 0.f, 0.f, 0.f);
#pragma unroll
    for (int i = 0; i < 8; i++) {
        int f  = i * NTHREADS + tid;
        int m  = f >> 5;
        int k4 = f & 31;
        float4 v = (m0 + m < M)
            ? __ldg((const float4*)(A + (size_t)(m0 + m) * D) + k4) : z4;
        *(float4*)(As + m * LDA + k4 * 4) = v;
    }
#pragma unroll
    for (int i = 0; i < 8; i++) {
        int f  = i * NTHREADS + tid;
        int k  = f >> 5;
        int n4 = f & 31;
        float4 v = __ldg((const float4*)(W + (size_t)k * D) + n4);
        *(float4*)(Ws + k * LDA + n4 * 4) = v;
    }
    __syncthreads();

    const int ty  = tid >> 4;       // 0..31
    const int tx  = tid & 15;       // 0..15
    const int row = ty * 4;
    const int col = tx * 8;

    float acc[4][8];
#pragma unroll
    for (int i = 0; i < 4; i++)
#pragma unroll
        for (int j = 0; j < 8; j++) acc[i][j] = 0.0f;

#pragma unroll 8
    for (int k = 0; k < D; k++) {
        float b[8];
        float4 t0 = *(const float4*)(Ws + k * LDA + col);
        float4 t1 = *(const float4*)(Ws + k * LDA + col + 4);
        b[0] = t0.x; b[1] = t0.y; b[2] = t0.z; b[3] = t0.w;
        b[4] = t1.x; b[5] = t1.y; b[6] = t1.z; b[7] = t1.w;
        float a[4];
#pragma unroll
        for (int i = 0; i < 4; i++) a[i] = As[(row + i) * LDA + k];
#pragma unroll
        for (int i = 0; i < 4; i++)
#pragma unroll
            for (int j = 0; j < 8; j++) acc[i][j] += a[i] * b[j];
    }

    if (mode == 0) {
        float bb[8];
        float4 t0 = __ldg((const float4*)(bias + col));
        float4 t1 = __ldg((const float4*)(bias + col + 4));
        bb[0]=t0.x; bb[1]=t0.y; bb[2]=t0.z; bb[3]=t0.w;
        bb[4]=t1.x; bb[5]=t1.y; bb[6]=t1.z; bb[7]=t1.w;
#pragma unroll
        for (int i = 0; i < 4; i++) {
            int m = m0 + row + i;
            if (m >= M) break;
            float d = g_dis[m];
            float d2 = d * d;
            float* cp  = C  + (size_t)m * D + col;
            float* cp2 = C2 + (size_t)m * D + col;
            float4 v0 = make_float4(acc[i][0], acc[i][1], acc[i][2], acc[i][3]);
            float4 v1 = make_float4(acc[i][4], acc[i][5], acc[i][6], acc[i][7]);
            *(float4*)cp       = v0;
            *(float4*)(cp + 4) = v1;
            *(float4*)cp2       = make_float4(fmaf(v0.x, d2, bb[0]), fmaf(v0.y, d2, bb[1]),
                                              fmaf(v0.z, d2, bb[2]), fmaf(v0.w, d2, bb[3]));
            *(float4*)(cp2 + 4) = make_float4(fmaf(v1.x, d2, bb[4]), fmaf(v1.y, d2, bb[5]),
                                              fmaf(v1.z, d2, bb[6]), fmaf(v1.w, d2, bb[7]));
        }
    } else {
        float bb[8];
        float4 t0 = __ldg((const float4*)(bias + col));
        float4 t1 = __ldg((const float4*)(bias + col + 4));
        bb[0]=t0.x; bb[1]=t0.y; bb[2]=t0.z; bb[3]=t0.w;
        bb[4]=t1.x; bb[5]=t1.y; bb[6]=t1.z; bb[7]=t1.w;
#pragma unroll
        for (int i = 0; i < 4; i++) {
            int m = m0 + row + i;
            if (m >= M) break;
            float out[8];
#pragma unroll
            for (int j = 0; j < 8; j++) {
                float v = acc[i][j] + bb[j];
                out[j] = (mode == 1) ? fmaxf(v, 0.0f) : v;
            }
            float* cp = C + (size_t)m * D + col;
            *(float4*)cp       = make_float4(out[0], out[1], out[2], out[3]);
            *(float4*)(cp + 4) = make_float4(out[4], out[5], out[6], out[7]);
        }
    }
}

// -------- gather: out[v] = relu( init[v] + sum_{e: dst=v} w_e * h[src_e] ) --------
// one warp per node; lane owns one float4 of the 128-float row
__global__ void gather_kernel(float* __restrict__ out) {
    int node = blockIdx.x * 8 + (threadIdx.x >> 5);
    int lane = threadIdx.x & 31;
    if (node >= N_NODES) return;

    int beg = g_off[node];
    int cnt = g_cnt[node];
    float4 acc = *((const float4*)(g_agg + (size_t)node * D) + lane);

    for (int j = 0; j < cnt; j++) {
        int   s = __ldg(&g_csrc[beg + j]);
        float w = __ldg(&g_cw[beg + j]);
        float4 v = __ldg((const float4*)(g_h + (size_t)s * D) + lane);
        acc.x = fmaf(w, v.x, acc.x);
        acc.y = fmaf(w, v.y, acc.y);
        acc.z = fmaf(w, v.z, acc.z);
        acc.w = fmaf(w, v.w, acc.w);
    }
    acc.x = fmaxf(acc.x, 0.0f);
    acc.y = fmaxf(acc.y, 0.0f);
    acc.z = fmaxf(acc.z, 0.0f);
    acc.w = fmaxf(acc.w, 0.0f);
    *((float4*)(out + (size_t)node * D) + lane) = acc;
}

extern "C" void kernel_launch(void* const* d_in, const int* in_sizes, int n_in,
                              void* d_out, int out_size)
{
    const float* x    = (const float*)d_in[0];
    const int*   ei   = (const int*)  d_in[1];
    const float* xa   = (const float*)d_in[2];
    const int*   eia  = (const int*)  d_in[3];
    const float* W_in = (const float*)d_in[4];
    const float* b_in = (const float*)d_in[5];
    const float* W_h  = (const float*)d_in[6];
    const float* b_h  = (const float*)d_in[7];
    const float* W_out= (const float*)d_in[8];
    const float* b_out= (const float*)d_in[9];
    const float* Wf1  = (const float*)d_in[10];
    const float* bf1  = (const float*)d_in[11];
    const float* Wf2  = (const float*)d_in[12];
    const float* bf2  = (const float*)d_in[13];
    float* out = (float*)d_out;

    cudaFuncSetAttribute(gemm_kernel,
        cudaFuncAttributeMaxDynamicSharedMemorySize, GEMM_SMEM);

    float *hp, *aggp, *bufp;
    cudaGetSymbolAddress((void**)&hp,   g_h);
    cudaGetSymbolAddress((void**)&aggp, g_agg);
    cudaGetSymbolAddress((void**)&bufp, g_buf);

    const int gemm_blocks  = (N_NODES + BM - 1) / BM;   // 391
    const int node_blocks  = (N_NODES + 255) / 256;     // 196
    const int edge_blocks  = (NE + 255) / 256;          // 3125
    const int gather_blocks = (N_NODES + 7) / 8;        // 6250

    const float* Wl[3] = {W_in, W_h, W_out};
    const float* bl[3] = {b_in, b_h, b_out};

    for (int g = 0; g < 2; g++) {
        const float* X   = g ? xa : x;
        const int*   src = (g ? eia : ei);
        const int*   dst = src + NE;
        float* OUT = out + (size_t)g * N_NODES * D;

        // CSR build + normalization
        zero_kernel<<<node_blocks, 256>>>();
        count_kernel<<<edge_blocks, 256>>>(dst);
        dis_kernel<<<node_blocks, 256>>>();
        scan1_kernel<<<SCAN_NBLK, 1024>>>();
        scan2_kernel<<<1, 64>>>();
        scan3_kernel<<<node_blocks, 256>>>();
        fill_kernel<<<edge_blocks, 256>>>(src, dst);

        // 3 GCN layers: GEMM (writes h and agg-init) then CSR gather (+relu)
        const float* in = X;
        for (int l = 0; l < 3; l++) {
            gemm_kernel<<<gemm_blocks, NTHREADS, GEMM_SMEM>>>(
                in, Wl[l], bl[l], hp, aggp, N_NODES, 0);
            gather_kernel<<<gather_blocks, 256>>>(bufp);
            in = bufp;
        }

        // MLP head
        gemm_kernel<<<gemm_blocks, NTHREADS, GEMM_SMEM>>>(
            bufp, Wf1, bf1, hp, nullptr, N_NODES, 1);
        gemm_kernel<<<gemm_blocks, NTHREADS, GEMM_SMEM>>>(
            hp, Wf2, bf2, OUT, nullptr, N_NODES, 2);
    }
}

// round 4
// speedup vs baseline: 1.6341x; 1.3504x over previous
#include <cuda_runtime.h>
#include <cstdint>

#define N_NODES 50000
#define D 128
#define NE 800000
#define BM 128
#define SCAN_NBLK ((N_NODES + 1023) / 1024)   // 49
#define GEMM_SMEM (2 * 128 * 128 * 4)          // As 64KB + Ws 64KB

// -------- device scratch --------
__device__ float g_h[(size_t)N_NODES * D];
__device__ float g_agg[(size_t)N_NODES * D];
__device__ float g_buf[(size_t)N_NODES * D];
__device__ float g_dis[N_NODES];
__device__ int   g_cnt[N_NODES];
__device__ int   g_off[N_NODES];
__device__ int   g_cur[N_NODES];
__device__ int   g_csrc[NE];
__device__ float g_cw[NE];
__device__ int   g_bsum[64];

// packed f32x2 helpers (baseline sm_100+ PTX, not 'a'-gated)
#define PACK_AA(out, af) \
    asm("mov.b64 %0, {%1, %1};" : "=l"(out) : "r"(af))
#define FMA2(d, a, b, c) \
    asm("fma.rn.f32x2 %0, %1, %2, %3;" : "=l"(d) : "l"(a), "l"(b), "l"(c))
#define UNPACK2(lo, hi, in) \
    asm("mov.b64 {%0, %1}, %2;" : "=f"(lo), "=f"(hi) : "l"(in))

// -------- CSR build --------
__global__ void zero_kernel() {
    int i = blockIdx.x * blockDim.x + threadIdx.x;
    if (i < N_NODES) { g_cnt[i] = 0; g_cur[i] = 0; }
}
__global__ void count_kernel(const int* __restrict__ dst) {
    int e = blockIdx.x * blockDim.x + threadIdx.x;
    if (e < NE) atomicAdd(&g_cnt[dst[e]], 1);
}
__global__ void dis_kernel() {
    int i = blockIdx.x * blockDim.x + threadIdx.x;
    if (i < N_NODES) g_dis[i] = rsqrtf((float)g_cnt[i] + 1.0f);
}
__global__ void scan1_kernel() {
    __shared__ int sh[1024];
    int i = blockIdx.x * 1024 + threadIdx.x;
    int v = (i < N_NODES) ? g_cnt[i] : 0;
    sh[threadIdx.x] = v;
    __syncthreads();
#pragma unroll
    for (int ofs = 1; ofs < 1024; ofs <<= 1) {
        int t = (threadIdx.x >= ofs) ? sh[threadIdx.x - ofs] : 0;
        __syncthreads();
        sh[threadIdx.x] += t;
        __syncthreads();
    }
    if (i < N_NODES) g_off[i] = sh[threadIdx.x] - v;
    if (threadIdx.x == 1023) g_bsum[blockIdx.x] = sh[1023];
}
__global__ void scan2_kernel() {
    __shared__ int sh[64];
    int v = (threadIdx.x < SCAN_NBLK) ? g_bsum[threadIdx.x] : 0;
    sh[threadIdx.x] = v;
    __syncthreads();
#pragma unroll
    for (int ofs = 1; ofs < 64; ofs <<= 1) {
        int t = (threadIdx.x >= ofs) ? sh[threadIdx.x - ofs] : 0;
        __syncthreads();
        sh[threadIdx.x] += t;
        __syncthreads();
    }
    if (threadIdx.x < SCAN_NBLK) g_bsum[threadIdx.x] = sh[threadIdx.x] - v;
}
__global__ void scan3_kernel() {
    int i = blockIdx.x * blockDim.x + threadIdx.x;
    if (i < N_NODES) g_off[i] += g_bsum[i >> 10];
}
__global__ void fill_kernel(const int* __restrict__ src, const int* __restrict__ dst) {
    int e = blockIdx.x * blockDim.x + threadIdx.x;
    if (e >= NE) return;
    int s = src[e], d = dst[e];
    int p = g_off[d] + atomicAdd(&g_cur[d], 1);
    g_csrc[p] = s;
    g_cw[p]   = g_dis[s] * g_dis[d];
}

// -------- GEMM: C[M,128] = A[M,128] @ W[128,128] (+ epilogue), f32x2 FMAs --------
// mode 0: C = h, C2 = h*dis[m]^2 + bias
// mode 1: C = relu(h + bias)
// mode 2: C = h + bias
__global__ __launch_bounds__(256, 1)
void gemm_kernel(const float* __restrict__ A, const float* __restrict__ W,
                 const float* __restrict__ bias,
                 float* __restrict__ C, float* __restrict__ C2,
                 int M, int mode)
{
    extern __shared__ float smem[];
    float* As = smem;               // [128][128] row-major
    float* Ws = smem + 128 * 128;   // [k][n] row-major (== W layout)

    const int tid = threadIdx.x;
    const int m0  = blockIdx.x * BM;

    // load A tile (128x128 fp32), zero-fill OOB rows
    const float4 z4 = make_float4(0.f, 0.f, 0.f, 0.f);
#pragma unroll
    for (int i = 0; i < 16; i++) {
        int f  = i * 256 + tid;       // float4 index
        int m  = f >> 5;
        int k4 = f & 31;
        float4 v = (m0 + m < M)
            ? __ldg((const float4*)(A + (size_t)(m0 + m) * D) + k4) : z4;
        *(float4*)(As + m * D + k4 * 4) = v;
    }
    // load W (direct 64KB copy, k-major rows = B operand layout)
#pragma unroll
    for (int i = 0; i < 16; i++) {
        int f = i * 256 + tid;
        ((float4*)Ws)[f] = __ldg((const float4*)W + f);
    }
    __syncthreads();

    const int ty  = tid >> 4;     // 0..15
    const int tx  = tid & 15;     // 0..15
    const int row = ty * 8;
    const int col = tx * 8;

    unsigned long long acc[8][4];
#pragma unroll
    for (int i = 0; i < 8; i++)
#pragma unroll
        for (int j = 0; j < 4; j++) acc[i][j] = 0ull;

#pragma unroll 4
    for (int k = 0; k < D; k++) {
        ulonglong2 b01 = *(const ulonglong2*)(Ws + k * D + col);       // cols (c0,c1),(c2,c3)
        ulonglong2 b23 = *(const ulonglong2*)(Ws + k * D + col + 4);   // (c4,c5),(c6,c7)
        unsigned long long b[4] = {b01.x, b01.y, b23.x, b23.y};
#pragma unroll
        for (int i = 0; i < 8; i++) {
            unsigned long long aa;
            PACK_AA(aa, __float_as_uint(As[(row + i) * D + k]));
#pragma unroll
            for (int j = 0; j < 4; j++) FMA2(acc[i][j], aa, b[j], acc[i][j]);
        }
    }

    // epilogue
    float bb[8];
    {
        float4 t0 = __ldg((const float4*)(bias + col));
        float4 t1 = __ldg((const float4*)(bias + col + 4));
        bb[0]=t0.x; bb[1]=t0.y; bb[2]=t0.z; bb[3]=t0.w;
        bb[4]=t1.x; bb[5]=t1.y; bb[6]=t1.z; bb[7]=t1.w;
    }
#pragma unroll
    for (int i = 0; i < 8; i++) {
        int m = m0 + row + i;
        if (m >= M) break;
        float v[8];
#pragma unroll
        for (int j = 0; j < 4; j++) UNPACK2(v[2*j], v[2*j+1], acc[i][j]);

        if (mode == 0) {
            float dd = g_dis[m];
            float d2 = dd * dd;
            float* cp  = C  + (size_t)m * D + col;
            float* cp2 = C2 + (size_t)m * D + col;
            *(float4*)cp       = make_float4(v[0], v[1], v[2], v[3]);
            *(float4*)(cp + 4) = make_float4(v[4], v[5], v[6], v[7]);
            *(float4*)cp2       = make_float4(fmaf(v[0], d2, bb[0]), fmaf(v[1], d2, bb[1]),
                                              fmaf(v[2], d2, bb[2]), fmaf(v[3], d2, bb[3]));
            *(float4*)(cp2 + 4) = make_float4(fmaf(v[4], d2, bb[4]), fmaf(v[5], d2, bb[5]),
                                              fmaf(v[6], d2, bb[6]), fmaf(v[7], d2, bb[7]));
        } else {
            float o[8];
#pragma unroll
            for (int j = 0; j < 8; j++) {
                float t = v[j] + bb[j];
                o[j] = (mode == 1) ? fmaxf(t, 0.0f) : t;
            }
            float* cp = C + (size_t)m * D + col;
            *(float4*)cp       = make_float4(o[0], o[1], o[2], o[3]);
            *(float4*)(cp + 4) = make_float4(o[4], o[5], o[6], o[7]);
        }
    }
}

// -------- gather: out[v] = relu( init[v] + sum_{e: dst=v} w_e * h[src_e] ) --------
__global__ void gather_kernel(float* __restrict__ out) {
    int node = blockIdx.x * 8 + (threadIdx.x >> 5);
    int lane = threadIdx.x & 31;
    if (node >= N_NODES) return;
    int beg = g_off[node];
    int cnt = g_cnt[node];
    float4 a0 = *((const float4*)(g_agg + (size_t)node * D) + lane);
    float4 a1 = make_float4(0.f, 0.f, 0.f, 0.f);

    int j = 0;
    for (; j + 2 <= cnt; j += 2) {
        int   s0 = __ldg(&g_csrc[beg + j]);
        int   s1 = __ldg(&g_csrc[beg + j + 1]);
        float w0 = __ldg(&g_cw[beg + j]);
        float w1 = __ldg(&g_cw[beg + j + 1]);
        float4 v0 = __ldg((const float4*)(g_h + (size_t)s0 * D) + lane);
        float4 v1 = __ldg((const float4*)(g_h + (size_t)s1 * D) + lane);
        a0.x = fmaf(w0, v0.x, a0.x); a0.y = fmaf(w0, v0.y, a0.y);
        a0.z = fmaf(w0, v0.z, a0.z); a0.w = fmaf(w0, v0.w, a0.w);
        a1.x = fmaf(w1, v1.x, a1.x); a1.y = fmaf(w1, v1.y, a1.y);
        a1.z = fmaf(w1, v1.z, a1.z); a1.w = fmaf(w1, v1.w, a1.w);
    }
    if (j < cnt) {
        int   s = __ldg(&g_csrc[beg + j]);
        float w = __ldg(&g_cw[beg + j]);
        float4 v = __ldg((const float4*)(g_h + (size_t)s * D) + lane);
        a0.x = fmaf(w, v.x, a0.x); a0.y = fmaf(w, v.y, a0.y);
        a0.z = fmaf(w, v.z, a0.z); a0.w = fmaf(w, v.w, a0.w);
    }
    a0.x = fmaxf(a0.x + a1.x, 0.0f);
    a0.y = fmaxf(a0.y + a1.y, 0.0f);
    a0.z = fmaxf(a0.z + a1.z, 0.0f);
    a0.w = fmaxf(a0.w + a1.w, 0.0f);
    *((float4*)(out + (size_t)node * D) + lane) = a0;
}

extern "C" void kernel_launch(void* const* d_in, const int* in_sizes, int n_in,
                              void* d_out, int out_size)
{
    const float* x    = (const float*)d_in[0];
    const int*   ei   = (const int*)  d_in[1];
    const float* xa   = (const float*)d_in[2];
    const int*   eia  = (const int*)  d_in[3];
    const float* W_in = (const float*)d_in[4];
    const float* b_in = (const float*)d_in[5];
    const float* W_h  = (const float*)d_in[6];
    const float* b_h  = (const float*)d_in[7];
    const float* W_out= (const float*)d_in[8];
    const float* b_out= (const float*)d_in[9];
    const float* Wf1  = (const float*)d_in[10];
    const float* bf1  = (const float*)d_in[11];
    const float* Wf2  = (const float*)d_in[12];
    const float* bf2  = (const float*)d_in[13];
    float* out = (float*)d_out;

    cudaFuncSetAttribute(gemm_kernel,
        cudaFuncAttributeMaxDynamicSharedMemorySize, GEMM_SMEM);

    float *hp, *aggp, *bufp;
    cudaGetSymbolAddress((void**)&hp,   g_h);
    cudaGetSymbolAddress((void**)&aggp, g_agg);
    cudaGetSymbolAddress((void**)&bufp, g_buf);

    const int gemm_blocks   = (N_NODES + BM - 1) / BM;   // 391
    const int node_blocks   = (N_NODES + 255) / 256;
    const int edge_blocks   = (NE + 255) / 256;
    const int gather_blocks = (N_NODES + 7) / 8;

    const float* Wl[3] = {W_in, W_h, W_out};
    const float* bl[3] = {b_in, b_h, b_out};

    for (int g = 0; g < 2; g++) {
        const float* X   = g ? xa : x;
        const int*   src = (g ? eia : ei);
        const int*   dst = src + NE;
        float* OUT = out + (size_t)g * N_NODES * D;

        zero_kernel<<<node_blocks, 256>>>();
        count_kernel<<<edge_blocks, 256>>>(dst);
        dis_kernel<<<node_blocks, 256>>>();
        scan1_kernel<<<SCAN_NBLK, 1024>>>();
        scan2_kernel<<<1, 64>>>();
        scan3_kernel<<<node_blocks, 256>>>();
        fill_kernel<<<edge_blocks, 256>>>(src, dst);

        const float* in = X;
        for (int l = 0; l < 3; l++) {
            gemm_kernel<<<gemm_blocks, 256, GEMM_SMEM>>>(
                in, Wl[l], bl[l], hp, aggp, N_NODES, 0);
            gather_kernel<<<gather_blocks, 256>>>(bufp);
            in = bufp;
        }

        gemm_kernel<<<gemm_blocks, 256, GEMM_SMEM>>>(
            bufp, Wf1, bf1, hp, nullptr, N_NODES, 1);
        gemm_kernel<<<gemm_blocks, 256, GEMM_SMEM>>>(
            hp, Wf2, bf2, OUT, nullptr, N_NODES, 2);
    }
}